// round 6
// baseline (speedup 1.0000x reference)
#include <cuda_runtime.h>
#include <cuda_fp16.h>
#include <cstdint>

// BlockLinear: y[b, nb*256+o] = sum_i x[b, nb*256+i]*w[nb,o,i] + bias
// fp32 in/out; fp16 HMMA m16n8k16. CTA 128x128, 4 warps of 64x64, BK=32,
// double-buffered smem, ldmatrix fragments, 2 CTAs/SM.

#define THREADS 128
#define ROWB 80                 // smem row stride bytes: (5r+c)%8 distinct -> ldmatrix conflict-free
#define ASTG (128 * ROWB)       // 10240 B per tile
#define STG  (2 * ASTG)         // 20480 B per stage (A + B)

__device__ __forceinline__ uint32_t pk2(float a, float b) {
    __half2 h = __floats2half2_rn(a, b);
    return *reinterpret_cast<uint32_t*>(&h);
}

__device__ __forceinline__ void ldm4(uint32_t* r, uint32_t addr) {
    asm volatile("ldmatrix.sync.aligned.m8n8.x4.shared.b16 {%0,%1,%2,%3}, [%4];"
                 : "=r"(r[0]), "=r"(r[1]), "=r"(r[2]), "=r"(r[3]) : "r"(addr));
}

__device__ __forceinline__ void mma16816(float* c, const uint32_t* a, const uint32_t* b) {
    asm volatile(
        "mma.sync.aligned.m16n8k16.row.col.f32.f16.f16.f32 "
        "{%0,%1,%2,%3},{%4,%5,%6,%7},{%8,%9},{%0,%1,%2,%3};"
        : "+f"(c[0]), "+f"(c[1]), "+f"(c[2]), "+f"(c[3])
        : "r"(a[0]), "r"(a[1]), "r"(a[2]), "r"(a[3]), "r"(b[0]), "r"(b[1]));
}

__global__ __launch_bounds__(THREADS, 2)
void block_linear_f16(const float* __restrict__ X, const float* __restrict__ W,
                      const float* __restrict__ Bias, float* __restrict__ Y)
{
    __shared__ __align__(16) unsigned char smT[2 * STG];   // 40960 B
    __shared__ float smBias[128];

    const int nb = blockIdx.z;
    const int m0 = blockIdx.y << 7;
    const int n0 = blockIdx.x << 7;

    const int tid  = threadIdx.x;
    const int warp = tid >> 5;
    const int lane = tid & 31;
    const int wm   = warp & 1;          // 2 warps along M (64 rows each)
    const int wn   = warp >> 1;         // 2 warps along N (64 cols each)
    const int g    = lane >> 2;
    const int tg   = lane & 3;

    smBias[tid] = Bias[nb * 256 + n0 + tid];

    // ---- tile-fill mapping: thread -> rows {frow, frow+64}, 16-float half fc ----
    const int frow = tid >> 1;          // 0..63
    const int fc   = tid & 1;           // half: 16 floats
    const float* xg = X + (size_t)(m0 + frow) * 16384 + nb * 256 + fc * 16;
    const float* wg = W + (size_t)nb * 65536 + (size_t)(n0 + frow) * 256 + fc * 16;
    unsigned char* sA0 = smT;
    unsigned char* sB0 = smT + ASTG;
    const uint32_t aoff = frow * ROWB + fc * 32;

    // ---- ldmatrix lane addressing ----
    const uint32_t smT_u = (uint32_t)__cvta_generic_to_shared(smT);
    const int la = lane & 15, ha = lane >> 4;                 // A: row 0-15 / k-half
    const uint32_t aAddr = smT_u + (wm * 64 + la) * ROWB + ha * 16;
    const int lb = (lane & 7) + ((lane >> 4) << 3);           // B: n row in 16-group
    const int cb = (lane >> 3) & 1;                           // B: k-half
    const uint32_t bAddr = smT_u + ASTG + (wn * 64 + lb) * ROWB + cb * 16;

    float acc[4][8][4];
    #pragma unroll
    for (int mt = 0; mt < 4; ++mt)
        #pragma unroll
        for (int nt = 0; nt < 8; ++nt)
            #pragma unroll
            for (int i = 0; i < 4; ++i) acc[mt][nt][i] = 0.0f;

    // ---- prologue: fill chunk 0 into stage 0 ----
    #pragma unroll
    for (int i = 0; i < 2; ++i) {
        const float* xr = xg + (size_t)i * 64 * 16384;
        const float* wr = wg + (size_t)i * 64 * 256;
        float4 a0 = *(const float4*)(xr);     float4 a1 = *(const float4*)(xr + 4);
        float4 a2 = *(const float4*)(xr + 8); float4 a3 = *(const float4*)(xr + 12);
        uint4 va0 = {pk2(a0.x, a0.y), pk2(a0.z, a0.w), pk2(a1.x, a1.y), pk2(a1.z, a1.w)};
        uint4 va1 = {pk2(a2.x, a2.y), pk2(a2.z, a2.w), pk2(a3.x, a3.y), pk2(a3.z, a3.w)};
        *(uint4*)(sA0 + i * 64 * ROWB + aoff)      = va0;
        *(uint4*)(sA0 + i * 64 * ROWB + aoff + 16) = va1;
        float4 b0 = *(const float4*)(wr);     float4 b1 = *(const float4*)(wr + 4);
        float4 b2 = *(const float4*)(wr + 8); float4 b3 = *(const float4*)(wr + 12);
        uint4 vb0 = {pk2(b0.x, b0.y), pk2(b0.z, b0.w), pk2(b1.x, b1.y), pk2(b1.z, b1.w)};
        uint4 vb1 = {pk2(b2.x, b2.y), pk2(b2.z, b2.w), pk2(b3.x, b3.y), pk2(b3.z, b3.w)};
        *(uint4*)(sB0 + i * 64 * ROWB + aoff)      = vb0;
        *(uint4*)(sB0 + i * 64 * ROWB + aoff + 16) = vb1;
    }
    __syncthreads();

    #pragma unroll 1
    for (int kc = 0; kc < 8; ++kc) {
        const int st = kc & 1;

        // prefetch next A chunk (X streams from DRAM) into regs
        float4 pa[8];
        if (kc < 7) {
            const int kb = (kc + 1) * 32;
            #pragma unroll
            for (int i = 0; i < 2; ++i) {
                const float* xr = xg + (size_t)i * 64 * 16384 + kb;
                pa[4 * i]     = *(const float4*)(xr);
                pa[4 * i + 1] = *(const float4*)(xr + 4);
                pa[4 * i + 2] = *(const float4*)(xr + 8);
                pa[4 * i + 3] = *(const float4*)(xr + 12);
            }
        }

        // ---- compute stage st: 2 k16-steps, warp tile 64x64 ----
        const uint32_t aB = aAddr + st * STG;
        const uint32_t bB = bAddr + st * STG;
        #pragma unroll
        for (int ks = 0; ks < 2; ++ks) {
            uint32_t aF[4][4], bF[8][2];
            #pragma unroll
            for (int mt = 0; mt < 4; ++mt)
                ldm4(aF[mt], aB + mt * 16 * ROWB + ks * 32);
            #pragma unroll
            for (int p = 0; p < 4; ++p) {
                uint32_t t[4];
                ldm4(t, bB + p * 16 * ROWB + ks * 32);
                bF[2 * p][0]     = t[0]; bF[2 * p][1]     = t[1];
                bF[2 * p + 1][0] = t[2]; bF[2 * p + 1][1] = t[3];
            }
            #pragma unroll
            for (int nt = 0; nt < 8; ++nt)
                #pragma unroll
                for (int mt = 0; mt < 4; ++mt)
                    mma16816(acc[mt][nt], aF[mt], bF[nt]);
        }

        // ---- fill next stage: B from L2, A from prefetch regs ----
        if (kc < 7) {
            const int kb  = (kc + 1) * 32;
            const int stn = st ^ 1;
            #pragma unroll
            for (int i = 0; i < 2; ++i) {
                const float* wr = wg + (size_t)i * 64 * 256 + kb;
                float4 b0 = *(const float4*)(wr);     float4 b1 = *(const float4*)(wr + 4);
                float4 b2 = *(const float4*)(wr + 8); float4 b3 = *(const float4*)(wr + 12);
                uint4 vb0 = {pk2(b0.x, b0.y), pk2(b0.z, b0.w), pk2(b1.x, b1.y), pk2(b1.z, b1.w)};
                uint4 vb1 = {pk2(b2.x, b2.y), pk2(b2.z, b2.w), pk2(b3.x, b3.y), pk2(b3.z, b3.w)};
                *(uint4*)(sB0 + stn * STG + i * 64 * ROWB + aoff)      = vb0;
                *(uint4*)(sB0 + stn * STG + i * 64 * ROWB + aoff + 16) = vb1;
                uint4 va0 = {pk2(pa[4*i].x, pa[4*i].y),     pk2(pa[4*i].z, pa[4*i].w),
                             pk2(pa[4*i+1].x, pa[4*i+1].y), pk2(pa[4*i+1].z, pa[4*i+1].w)};
                uint4 va1 = {pk2(pa[4*i+2].x, pa[4*i+2].y), pk2(pa[4*i+2].z, pa[4*i+2].w),
                             pk2(pa[4*i+3].x, pa[4*i+3].y), pk2(pa[4*i+3].z, pa[4*i+3].w)};
                *(uint4*)(sA0 + stn * STG + i * 64 * ROWB + aoff)      = va0;
                *(uint4*)(sA0 + stn * STG + i * 64 * ROWB + aoff + 16) = va1;
            }
            __syncthreads();
        }
    }

    // ---- epilogue: bias + fp32 stores ----
    #pragma unroll
    for (int mt = 0; mt < 4; ++mt) {
        const int row0 = m0 + wm * 64 + mt * 16 + g;
        #pragma unroll
        for (int nt = 0; nt < 8; ++nt) {
            const int lcol = wn * 64 + nt * 8 + tg * 2;     // 0..127
            const int gcol = nb * 256 + n0 + lcol;
            const float b0 = smBias[lcol];
            const float b1 = smBias[lcol + 1];
            float2 v0 = make_float2(acc[mt][nt][0] + b0, acc[mt][nt][1] + b1);
            float2 v1 = make_float2(acc[mt][nt][2] + b0, acc[mt][nt][3] + b1);
            *reinterpret_cast<float2*>(Y + (size_t)row0       * 16384 + gcol) = v0;
            *reinterpret_cast<float2*>(Y + (size_t)(row0 + 8) * 16384 + gcol) = v1;
        }
    }
}

extern "C" void kernel_launch(void* const* d_in, const int* in_sizes, int n_in,
                              void* d_out, int out_size) {
    const float* x    = (const float*)d_in[0];
    const float* w    = (const float*)d_in[1];
    const float* bias = (const float*)d_in[2];
    float* y          = (float*)d_out;

    dim3 grid(2, 32, 64);   // (n-tile, m-slab, diag block)
    block_linear_f16<<<grid, THREADS>>>(x, w, bias, y);
}

// round 9
// speedup vs baseline: 1.2279x; 1.2279x over previous
#include <cuda_runtime.h>
#include <cuda_fp16.h>
#include <cstdint>

// BlockLinear, weight-resident: each CTA owns one (nb, m-half): converts
// W[nb] (256x256) to fp16 SMEM once, then streams 16 M-slabs of 128 rows.
// CTA tile 128x256, 8 warps of 64x64 (2M x 4N), K chunks of 64, double-buffered A.

#define THREADS 256
#define ARB 144                    // A smem row bytes: 16*(8+1) -> conflict-free
#define BRB 528                    // B smem row bytes: 16*(32+1) -> conflict-free
#define A_STG (128 * ARB)          // 18432 B per A stage
#define SM_A 0
#define SM_B (2 * A_STG)           // 36864
#define SM_BIAS (SM_B + 256 * BRB) // 172032
#define SMEM_TOTAL (SM_BIAS + 1024)

__device__ __forceinline__ uint32_t pk2(float a, float b) {
    __half2 h = __floats2half2_rn(a, b);
    return *reinterpret_cast<uint32_t*>(&h);
}
__device__ __forceinline__ void ldm4(uint32_t* r, uint32_t addr) {
    asm volatile("ldmatrix.sync.aligned.m8n8.x4.shared.b16 {%0,%1,%2,%3}, [%4];"
                 : "=r"(r[0]), "=r"(r[1]), "=r"(r[2]), "=r"(r[3]) : "r"(addr));
}
__device__ __forceinline__ void mma16816(float* c, const uint32_t* a, const uint32_t* b) {
    asm volatile(
        "mma.sync.aligned.m16n8k16.row.col.f32.f16.f16.f32 "
        "{%0,%1,%2,%3},{%4,%5,%6,%7},{%8,%9},{%0,%1,%2,%3};"
        : "+f"(c[0]), "+f"(c[1]), "+f"(c[2]), "+f"(c[3])
        : "r"(a[0]), "r"(a[1]), "r"(a[2]), "r"(a[3]), "r"(b[0]), "r"(b[1]));
}

__global__ __launch_bounds__(THREADS, 1)
void block_linear_wres(const float* __restrict__ X, const float* __restrict__ W,
                       const float* __restrict__ Bias, float* __restrict__ Y)
{
    extern __shared__ unsigned char sm[];
    const uint32_t smu = (uint32_t)__cvta_generic_to_shared(sm);

    const int nb = blockIdx.x;          // diag block 0..63
    const int by = blockIdx.y;          // m-half 0..1 (16 slabs each)

    const int tid  = threadIdx.x;
    const int warp = tid >> 5;
    const int lane = tid & 31;
    const int wm   = warp & 1;          // 2 warps along M (64 rows)
    const int wn   = warp >> 1;         // 4 warps along N (64 cols)
    const int g    = lane >> 2;
    const int tg   = lane & 3;

    // ---- bias to smem ----
    ((float*)(sm + SM_BIAS))[tid] = Bias[nb * 256 + tid];

    // ---- one-time: convert W[nb] (256 rows x 256 k fp32) -> fp16 smem ----
    {
        const float4* wr = (const float4*)(W + (size_t)nb * 65536 + (size_t)tid * 256);
        unsigned char* brow = sm + SM_B + tid * BRB;
        #pragma unroll 8
        for (int j = 0; j < 32; ++j) {
            float4 v0 = wr[2 * j], v1 = wr[2 * j + 1];
            uint4 o = {pk2(v0.x, v0.y), pk2(v0.z, v0.w), pk2(v1.x, v1.y), pk2(v1.z, v1.w)};
            *(uint4*)(brow + j * 16) = o;
        }
    }

    // ---- A fill mapping: thread -> row r, 32-float segment seg ----
    const int r   = tid >> 1;           // 0..127
    const int seg = tid & 1;            // k-segment of 32 floats
    const float* xbase = X + (size_t)nb * 256 + seg * 32;
    unsigned char* aS = sm + SM_A;
    const uint32_t asts = (uint32_t)(r * ARB + seg * 64);

    // ---- ldmatrix lane addressing (validated R4 pattern) ----
    const int la = lane & 15, ha = lane >> 4;
    const uint32_t aAddr = smu + SM_A + (wm * 64 + la) * ARB + ha * 16;
    const int lb = (lane & 7) + ((lane >> 4) << 3);
    const int cb = (lane >> 3) & 1;
    const uint32_t bAddr = smu + SM_B + (wn * 64 + lb) * BRB + cb * 16;

    float acc[4][8][4];
    #pragma unroll
    for (int mt = 0; mt < 4; ++mt)
        #pragma unroll
        for (int nt = 0; nt < 8; ++nt)
            #pragma unroll
            for (int i = 0; i < 4; ++i) acc[mt][nt][i] = 0.0f;

    // ---- prologue: chunk 0 -> stage 0 ----
    {
        const int m0 = by * 2048;                       // slab 0 of this half
        const float* xr = xbase + (size_t)(m0 + r) * 16384;
        #pragma unroll
        for (int j = 0; j < 4; ++j) {
            float4 v0 = *(const float4*)(xr + j * 8);
            float4 v1 = *(const float4*)(xr + j * 8 + 4);
            uint4 o = {pk2(v0.x, v0.y), pk2(v0.z, v0.w), pk2(v1.x, v1.y), pk2(v1.z, v1.w)};
            *(uint4*)(aS + asts + j * 16) = o;
        }
    }
    __syncthreads();

    // ---- main loop: 64 chunks = 16 slabs x 4 K-chunks ----
    #pragma unroll 1
    for (int c = 0; c < 64; ++c) {
        const int p = c & 1;

        // prefetch next chunk's X into regs (hidden under compute)
        float4 pf[8];
        if (c < 63) {
            const int cn   = c + 1;
            const int m0n  = (by * 16 + (cn >> 2)) * 128;
            const int kbn  = (cn & 3) * 64;
            const float* xr = xbase + (size_t)(m0n + r) * 16384 + kbn;
            #pragma unroll
            for (int j = 0; j < 8; ++j)
                pf[j] = *(const float4*)(xr + j * 4);
        }

        // compute chunk c from stage p: 4 k16-steps
        const uint32_t aB = aAddr + p * A_STG;
        const uint32_t bB = bAddr + (c & 3) * 128;
        #pragma unroll
        for (int ks = 0; ks < 4; ++ks) {
            uint32_t aF[4][4], bF[8][2];
            #pragma unroll
            for (int mt = 0; mt < 4; ++mt)
                ldm4(aF[mt], aB + mt * 16 * ARB + ks * 32);
            #pragma unroll
            for (int q = 0; q < 4; ++q) {
                uint32_t t[4];
                ldm4(t, bB + q * 16 * BRB + ks * 32);
                bF[2 * q][0]     = t[0]; bF[2 * q][1]     = t[1];
                bF[2 * q + 1][0] = t[2]; bF[2 * q + 1][1] = t[3];
            }
            #pragma unroll
            for (int nt = 0; nt < 8; ++nt)
                #pragma unroll
                for (int mt = 0; mt < 4; ++mt)
                    mma16816(acc[mt][nt], aF[mt], bF[nt]);
        }

        // slab finished? epilogue + reset accs
        if ((c & 3) == 3) {
            const int m0 = (by * 16 + (c >> 2)) * 128;
            const float* bs = (const float*)(sm + SM_BIAS);
            #pragma unroll
            for (int mt = 0; mt < 4; ++mt) {
                const int row0 = m0 + wm * 64 + mt * 16 + g;
                #pragma unroll
                for (int nt = 0; nt < 8; ++nt) {
                    const int lcol = wn * 64 + nt * 8 + tg * 2;
                    const int gcol = nb * 256 + lcol;
                    const float b0 = bs[lcol], b1 = bs[lcol + 1];
                    float2 v0 = make_float2(acc[mt][nt][0] + b0, acc[mt][nt][1] + b1);
                    float2 v1 = make_float2(acc[mt][nt][2] + b0, acc[mt][nt][3] + b1);
                    *(float2*)(Y + (size_t)row0       * 16384 + gcol) = v0;
                    *(float2*)(Y + (size_t)(row0 + 8) * 16384 + gcol) = v1;
                    acc[mt][nt][0] = 0.0f; acc[mt][nt][1] = 0.0f;
                    acc[mt][nt][2] = 0.0f; acc[mt][nt][3] = 0.0f;
                }
            }
        }

        // store prefetched chunk into other stage
        if (c < 63) {
            unsigned char* dst = aS + (p ^ 1) * A_STG + asts;
            #pragma unroll
            for (int j = 0; j < 4; ++j) {
                uint4 o = {pk2(pf[2*j].x, pf[2*j].y),     pk2(pf[2*j].z, pf[2*j].w),
                           pk2(pf[2*j+1].x, pf[2*j+1].y), pk2(pf[2*j+1].z, pf[2*j+1].w)};
                *(uint4*)(dst + j * 16) = o;
            }
        }
        __syncthreads();
    }
}

extern "C" void kernel_launch(void* const* d_in, const int* in_sizes, int n_in,
                              void* d_out, int out_size) {
    const float* x    = (const float*)d_in[0];
    const float* w    = (const float*)d_in[1];
    const float* bias = (const float*)d_in[2];
    float* y          = (float*)d_out;

    cudaFuncSetAttribute(block_linear_wres,
                         cudaFuncAttributeMaxDynamicSharedMemorySize, SMEM_TOTAL);
    dim3 grid(64, 2);   // (diag block, m-half) -> 128 CTAs, one wave
    block_linear_wres<<<grid, THREADS, SMEM_TOTAL>>>(x, w, bias, y);
}